// round 11
// baseline (speedup 1.0000x reference)
#include <cuda_runtime.h>
#include <math.h>

#define BB    16
#define CIN   64
#define COUT  64
#define NN    16384
#define NF    8192      // complex FFT size (N/2)
#define MODES 2048
#define TEMB  512

typedef unsigned long long ull;

// Skewed shared index: every 8 complexes insert 1 pad -> tames smem bank
// conflicts of the strided Stockham stores.
#define IDX(a) ((a) + ((a) >> 3))
#define SBUF   9216      // IDX(8191)=9214 < 9216  -> 73728 bytes (single buffer)

// ---------------- scratch (static device memory; no allocation) -------------
__device__ float2 g_Xm[BB * CIN * MODES];   // forward modes (+temb bias)
__device__ float2 g_Om[BB * COUT * MODES];  // contracted modes
__device__ float  g_t [BB * CIN];           // temb bias per (b, c_in)

#define ASTEP (-7.66990393942820615e-4f)    // -2*pi/8192
#define BSTEP (-3.83495196971410307e-4f)    // -2*pi/16384

// ---------------- scalar complex helpers -------------------------------------
__device__ __forceinline__ float2 cmulf(float2 a, float2 b) {
    return make_float2(fmaf(a.x, b.x, -a.y * b.y), fmaf(a.x, b.y, a.y * b.x));
}
__device__ __forceinline__ float2 twid(float ang) {
    float s, c;
    __sincosf(ang, &s, &c);
    return make_float2(c, s);
}

// ---------------- packed f32x2 complex helpers (sm_103a) ---------------------
__device__ __forceinline__ ull f2u(float2 v) {
    return (ull)__float_as_uint(v.x) | ((ull)__float_as_uint(v.y) << 32);
}
__device__ __forceinline__ float2 u2f(ull v) {
    return make_float2(__uint_as_float((unsigned)v),
                       __uint_as_float((unsigned)(v >> 32)));
}
__device__ __forceinline__ ull pk(float x, float y) { return f2u(make_float2(x, y)); }

__device__ __forceinline__ ull padd(ull a, ull b) {
    ull d; asm("add.rn.f32x2 %0, %1, %2;" : "=l"(d) : "l"(a), "l"(b)); return d;
}
__device__ __forceinline__ ull pmul(ull a, ull b) {
    ull d; asm("mul.rn.f32x2 %0, %1, %2;" : "=l"(d) : "l"(a), "l"(b)); return d;
}
__device__ __forceinline__ ull pfma(ull a, ull b, ull c) {
    ull d; asm("fma.rn.f32x2 %0, %1, %2, %3;" : "=l"(d) : "l"(a), "l"(b), "l"(c)); return d;
}
// a - b  ==  fma(b, -1, a)  (exact product -> identical rounding to sub)
__device__ __forceinline__ ull psub(ull a, ull b) {
    return pfma(b, 0xBF800000BF800000ULL, a);      // (-1.0f, -1.0f)
}
// *  i : (x,y) -> (-y, x)
__device__ __forceinline__ ull pmuli(ull v) {
    return ((v >> 32) ^ 0x80000000ULL) | (v << 32);
}
// * -i : (x,y) -> (y, -x)
__device__ __forceinline__ ull pmulnegi(ull v) {
    return ((v ^ 0x80000000ULL) << 32) | (v >> 32);
}
__device__ __forceinline__ ull pdup_lo(ull a) { return (a & 0xFFFFFFFFULL) | (a << 32); }
__device__ __forceinline__ ull pdup_hi(ull a) { return (a >> 32) | (a & 0xFFFFFFFF00000000ULL); }
// a * w (w typically a compile-time constant -> pmuli(w) const-folds)
__device__ __forceinline__ ull pcmulc(ull a, ull w) {
    return pfma(pdup_lo(a), w, pmul(pdup_hi(a), pmuli(w)));
}

// packed DFT4 (forward), natural-order out
__device__ __forceinline__ void pdft4(ull a, ull b, ull c, ull d, ull y[4]) {
    ull t0 = padd(a, c), t1 = psub(a, c);
    ull t2 = padd(b, d), t3 = psub(b, d);
    y[0] = padd(t0, t2);
    y[2] = psub(t0, t2);
    ull it3 = pmuli(t3);
    y[1] = psub(t1, it3);          // t1 - i*t3
    y[3] = padd(t1, it3);          // t1 + i*t3
}

// packed DFT8 (forward), natural-order in/out
__device__ __forceinline__ void pfft8(ull v[8]) {
    const ull CC = 0x3F3504F33F3504F3ULL;          // (c, c), c = sqrt(2)/2
    ull e[4], o[4];
    pdft4(v[0], v[2], v[4], v[6], e);
    pdft4(v[1], v[3], v[5], v[7], o);
    ull o1 = pmul(padd(o[1], pmulnegi(o[1])), CC); // c*(x+y, y-x)
    ull o2 = pmulnegi(o[2]);                       // (y, -x)
    ull o3 = pmul(psub(pmulnegi(o[3]), o[3]), CC); // c*(y-x, -x-y)
    v[0] = padd(e[0], o[0]);  v[4] = psub(e[0], o[0]);
    v[1] = padd(e[1], o1);    v[5] = psub(e[1], o1);
    v[2] = padd(e[2], o2);    v[6] = psub(e[2], o2);
    v[3] = padd(e[3], o3);    v[7] = psub(e[3], o3);
}

// packed DFT16 (forward), natural-order in/out; N1=4 x N2=4 decomposition.
__device__ __forceinline__ void pfft16(ull v[16]) {
    const float c1 = 0.92387953251128675f;   // cos(pi/8)
    const float s1 = 0.38268343236508977f;   // sin(pi/8)
    const float c2 = 0.70710678118654752f;
    ull y0[4], y1[4], y2[4], y3[4];
    pdft4(v[0], v[4], v[8],  v[12], y0);
    pdft4(v[1], v[5], v[9],  v[13], y1);
    pdft4(v[2], v[6], v[10], v[14], y2);
    pdft4(v[3], v[7], v[11], v[15], y3);
    y1[1] = pcmulc(y1[1], pk( c1, -s1));
    y1[2] = pcmulc(y1[2], pk( c2, -c2));
    y1[3] = pcmulc(y1[3], pk( s1, -c1));
    y2[1] = pcmulc(y2[1], pk( c2, -c2));
    y2[2] = pmulnegi(y2[2]);
    y2[3] = pcmulc(y2[3], pk(-c2, -c2));
    y3[1] = pcmulc(y3[1], pk( s1, -c1));
    y3[2] = pcmulc(y3[2], pk(-c2, -c2));
    y3[3] = pcmulc(y3[3], pk(-c1,  s1));
    ull z[4];
    pdft4(y0[0], y1[0], y2[0], y3[0], z); v[0]=z[0]; v[4]=z[1]; v[8] =z[2]; v[12]=z[3];
    pdft4(y0[1], y1[1], y2[1], y3[1], z); v[1]=z[0]; v[5]=z[1]; v[9] =z[2]; v[13]=z[3];
    pdft4(y0[2], y1[2], y2[2], y3[2], z); v[2]=z[0]; v[6]=z[1]; v[10]=z[2]; v[14]=z[3];
    pdft4(y0[3], y1[3], y2[3], y3[3], z); v[3]=z[0]; v[7]=z[1]; v[11]=z[2]; v[15]=z[3];
}

// ---- middle radix-8 stages (s = 1, 2) of the 8192-pt Stockham FFT ----------
// Twiddles hoisted out of the h loop: (tid+512) & (Ns-1) == tid & (Ns-1).
__device__ void fft_stages12(float2* S) {
    const int tid = threadIdx.x;
#pragma unroll
    for (int s = 1; s < 3; s++) {
        const int Ns    = 1 << (3 * s);
        const int shift = 10 - 3 * s;
        const int t = tid & (Ns - 1);
        const float2 w1 = twid((float)(t << shift) * ASTEP);
        const float2 w2 = cmulf(w1, w1);
        const float2 w3 = cmulf(w2, w1);
        const float2 w4 = cmulf(w2, w2);
        const float2 w5 = cmulf(w4, w1);
        const float2 w6 = cmulf(w4, w2);
        const float2 w7 = cmulf(w4, w3);
        ull v[2][8];
        int base[2];
#pragma unroll
        for (int h = 0; h < 2; h++) {
            const int j = tid + (h << 9);
            float2 f[8];
#pragma unroll
            for (int r = 0; r < 8; r++) f[r] = S[IDX(j + (r << 10))];
            f[1] = cmulf(f[1], w1);  f[2] = cmulf(f[2], w2);
            f[3] = cmulf(f[3], w3);  f[4] = cmulf(f[4], w4);
            f[5] = cmulf(f[5], w5);  f[6] = cmulf(f[6], w6);
            f[7] = cmulf(f[7], w7);
#pragma unroll
            for (int r = 0; r < 8; r++) v[h][r] = f2u(f[r]);
            pfft8(v[h]);
            base[h] = ((j >> (3 * s)) << (3 * s + 3)) + t;  // (j/Ns)*8Ns + t
        }
        __syncthreads();
#pragma unroll
        for (int h = 0; h < 2; h++)
#pragma unroll
            for (int r = 0; r < 8; r++)
                *(ull*)&S[IDX(base[h] + (r << (3 * s)))] = v[h][r];
        __syncthreads();
    }
}

// ---- final radix-16 butterfly: load from S, twiddle, pfft16 -> vf[16] ------
__device__ __forceinline__ void radix16_body(const float2* S, int j, float2 vf[16]) {
    const float2 w1 = twid((float)j * ASTEP);
    const float2 w2 = cmulf(w1, w1);
    const float2 w3 = cmulf(w2, w1);
    const float2 w4 = cmulf(w2, w2);
    const float2 w5 = cmulf(w4, w1);
    const float2 w6 = cmulf(w4, w2);
    const float2 w7 = cmulf(w4, w3);
    const float2 w8 = cmulf(w4, w4);
    ull v[16];
    v[0]  = f2u(S[IDX(j)]);
    v[1]  = f2u(cmulf(S[IDX(j + (1  << 9))], w1));
    v[2]  = f2u(cmulf(S[IDX(j + (2  << 9))], w2));
    v[3]  = f2u(cmulf(S[IDX(j + (3  << 9))], w3));
    v[4]  = f2u(cmulf(S[IDX(j + (4  << 9))], w4));
    v[5]  = f2u(cmulf(S[IDX(j + (5  << 9))], w5));
    v[6]  = f2u(cmulf(S[IDX(j + (6  << 9))], w6));
    v[7]  = f2u(cmulf(S[IDX(j + (7  << 9))], w7));
    v[8]  = f2u(cmulf(S[IDX(j + (8  << 9))], w8));
    v[9]  = f2u(cmulf(S[IDX(j + (9  << 9))], cmulf(w8, w1)));
    v[10] = f2u(cmulf(S[IDX(j + (10 << 9))], cmulf(w8, w2)));
    v[11] = f2u(cmulf(S[IDX(j + (11 << 9))], cmulf(w8, w3)));
    v[12] = f2u(cmulf(S[IDX(j + (12 << 9))], cmulf(w8, w4)));
    v[13] = f2u(cmulf(S[IDX(j + (13 << 9))], cmulf(w8, w5)));
    v[14] = f2u(cmulf(S[IDX(j + (14 << 9))], cmulf(w8, w6)));
    v[15] = f2u(cmulf(S[IDX(j + (15 << 9))], cmulf(w8, w7)));
    pfft16(v);
#pragma unroll
    for (int r = 0; r < 16; r++) vf[r] = u2f(v[r]);
}

// ---------------- kernel: temb bias t[b,c] ----------------------------------
__global__ void k_bias(const float* __restrict__ temb,
                       const float* __restrict__ dw,
                       const float* __restrict__ db) {
    __shared__ float s_act[TEMB];
    __shared__ float s_part[256];
    const int b = blockIdx.x;
    const int tid = threadIdx.x;
    for (int k = tid; k < TEMB; k += 256) {
        float v = temb[b * TEMB + k];
        s_act[k] = v / (1.0f + expf(-v));          // SiLU
    }
    __syncthreads();
    const int c = tid & 63;
    const int p = tid >> 6;                        // 4 partial chunks of 128
    float sum = 0.0f;
    const float* w = dw + (size_t)c * TEMB;
    for (int k = p * 128; k < (p + 1) * 128; k++) sum = fmaf(s_act[k], w[k], sum);
    s_part[p * 64 + c] = sum;
    __syncthreads();
    if (tid < 64) {
        g_t[b * 64 + tid] = s_part[tid] + s_part[64 + tid] + s_part[128 + tid]
                          + s_part[192 + tid] + db[tid];
    }
}

// ---------------- kernel: forward rFFT + mode extraction + bias -------------
// Stage 0 fully packed, straight from gmem. Tail: modes m=tid+512r (r<4) come
// from radix-16 registers; only mirror halves (r>=12) round-trip shared.
__global__ void __launch_bounds__(512, 2)
k_fwd(const float* __restrict__ x) {
    extern __shared__ float2 sm[];
    float2* S = sm;
    const int row = blockIdx.x;                    // b*64 + c_in
    const ull* xr = (const ull*)x + (size_t)row * NF;
    const int tid = threadIdx.x;
    // stage 0: Ns=1, twiddle-free, packed, inputs straight from gmem
    {
        ull v[2][8];
#pragma unroll
        for (int h = 0; h < 2; h++) {
            const int j = tid + (h << 9);
#pragma unroll
            for (int r = 0; r < 8; r++) v[h][r] = __ldg(&xr[j + (r << 10)]);
            pfft8(v[h]);
        }
#pragma unroll
        for (int h = 0; h < 2; h++) {
            const int base = (tid + (h << 9)) << 3;
#pragma unroll
            for (int r = 0; r < 8; r++) *(ull*)&S[IDX(base + r)] = v[h][r];
        }
        __syncthreads();
    }
    fft_stages12(S);
    float2 v[16];
    radix16_body(S, tid, v);
    __syncthreads();               // stage-2 reads done before overwrite
    // store only the mirror groups r in [12,16): entries 6144..8191
#pragma unroll
    for (int r = 12; r < 16; r++) S[IDX(tid + (r << 9))] = v[r];
    __syncthreads();
    const float tb = g_t[row];
    float2* xrow = g_Xm + (size_t)row * MODES;
#pragma unroll
    for (int r = 0; r < 4; r++) {
        const int m = tid + (r << 9);
        float2 Zm = v[r];
        float2 Zn;
        if (tid == 0) {
            Zn = (r == 0) ? v[0] : v[16 - r];       // Z[8192-512r] is own reg
        } else {
            // 8192-m = (512-tid) + 512*(15-r) -> stored by thread 512-tid
            Zn = S[IDX((512 - tid) + ((15 - r) << 9))];
        }
        float2 A  = make_float2(Zm.x + Zn.x, Zm.y - Zn.y);   // Z + conj(Zn)
        float2 Bc = make_float2(Zm.x - Zn.x, Zm.y + Zn.y);   // Z - conj(Zn)
        float2 C  = cmulf(twid((float)m * BSTEP), Bc);
        // X = 0.5*A - 0.5*i*C ; add temb bias to real part
        xrow[m] = make_float2(0.5f * (A.x + C.y) + tb, 0.5f * (A.y - C.x));
    }
}

// ---------------- kernel: mode contraction (bim,iom->bom) -------------------
// grid: 256 blocks (8 modes each); block: 256 threads =
//   [bit7]=batch-half x [bits2:7]=32 o-pairs x [bits0:2]=4 mode-pairs.
// Round-8 layout + prefetch.global.L2 at distance 4 (verified winner).
__global__ void __launch_bounds__(256, 2)
k_einsum(const float* __restrict__ wr, const float* __restrict__ wi) {
    extern __shared__ float4 Xc[];                 // [ (b*64+i)*4 + mg ] 64KB
    const int m0  = blockIdx.x * 8;
    const int tid = threadIdx.x;
    for (int idx = tid; idx < BB * CIN * 4; idx += 256) {
        const int p  = idx & 3;
        const int bi = idx >> 2;
        float4 q = *((const float4*)(g_Xm + (size_t)bi * MODES + m0) + p);
        Xc[idx] = make_float4(q.x, q.z, q.y, q.w); // (re0, re1, im0, im1)
    }
    __syncthreads();
    const int mg = tid & 3;
    const int op = (tid >> 2) & 31;
    const int bh = tid >> 7;
    const int o0 = 2 * op;
    const int m  = m0 + 2 * mg;
    const int b0 = bh * 8;

    ull ar[2][8], ai[2][8];
#pragma unroll
    for (int k = 0; k < 2; k++)
#pragma unroll
        for (int b = 0; b < 8; b++) { ar[k][b] = 0ULL; ai[k][b] = 0ULL; }

    const size_t istep = (size_t)COUT * MODES;
    size_t off = (size_t)o0 * MODES + m;
    ull cwr0 = *(const ull*)(wr + off);
    ull cwr1 = *(const ull*)(wr + off + MODES);
    ull cwi0 = *(const ull*)(wi + off);
    ull cwi1 = *(const ull*)(wi + off + MODES);

    for (int i = 0; i < CIN; i++) {
        ull nwr0, nwr1, nwi0, nwi1;
        if (i + 1 < CIN) {                          // register prefetch, d=1
            const size_t noff = off + istep;
            nwr0 = *(const ull*)(wr + noff);
            nwr1 = *(const ull*)(wr + noff + MODES);
            nwi0 = *(const ull*)(wi + noff);
            nwi1 = *(const ull*)(wi + noff + MODES);
        }
        if (i + 4 < CIN) {                          // L2 prefetch, distance 4
            const size_t poff = off + 4 * istep;
            asm volatile("prefetch.global.L2 [%0];" :: "l"(wr + poff));
            asm volatile("prefetch.global.L2 [%0];" :: "l"(wr + poff + MODES));
            asm volatile("prefetch.global.L2 [%0];" :: "l"(wi + poff));
            asm volatile("prefetch.global.L2 [%0];" :: "l"(wi + poff + MODES));
        }
#pragma unroll
        for (int b = 0; b < 8; b++) {
            const int idx2 = ((b0 + b) * CIN + i) * 4 + mg;
            const ulonglong2 xu = *(const ulonglong2*)(Xc + idx2); // 1 LDS.128
            const ull xr2  = xu.x;                                 // (re0,re1)
            const ull xi2  = xu.y;                                 // (im0,im1)
            const ull xin2 = xi2 ^ 0x8000000080000000ULL;
            ar[0][b] = pfma(xr2,  cwr0, ar[0][b]);
            ar[0][b] = pfma(xin2, cwi0, ar[0][b]);
            ai[0][b] = pfma(xr2,  cwi0, ai[0][b]);
            ai[0][b] = pfma(xi2,  cwr0, ai[0][b]);
            ar[1][b] = pfma(xr2,  cwr1, ar[1][b]);
            ar[1][b] = pfma(xin2, cwi1, ar[1][b]);
            ai[1][b] = pfma(xr2,  cwi1, ai[1][b]);
            ai[1][b] = pfma(xi2,  cwr1, ai[1][b]);
        }
        cwr0 = nwr0; cwr1 = nwr1; cwi0 = nwi0; cwi1 = nwi1;
        off += istep;
    }
#pragma unroll
    for (int k = 0; k < 2; k++)
#pragma unroll
        for (int b = 0; b < 8; b++) {
            const float2 r2 = u2f(ar[k][b]);
            const float2 i2 = u2f(ai[k][b]);
            const size_t ob = ((size_t)((b0 + b) * COUT + o0 + k)) * MODES + m;
            *((float4*)(g_Om + ob)) = make_float4(r2.x, i2.x, r2.y, i2.y);
        }
}

// ---------------- kernel: inverse rFFT --------------------------------------
// Stage 0 builds the Hermitian-packed spectrum in REGISTERS from g_Om
// (only r in {0,1,6,7} nonzero); final radix-16 writes straight to gmem.
__global__ void __launch_bounds__(512, 2)
k_inv(float* __restrict__ out) {
    extern __shared__ float2 sm[];
    float2* S = sm;
    const int row = blockIdx.x;                    // b*64 + c_out
    const float2* orow = g_Om + (size_t)row * MODES;
    const int tid = threadIdx.x;
    // stage 0 (Ns=1, twiddle-free, packed): inputs computed inline
    {
        ull v[2][8];
#pragma unroll
        for (int h = 0; h < 2; h++) {
            const int j = tid + (h << 9);
#pragma unroll
            for (int r = 0; r < 8; r++) {
                if (r >= 2 && r <= 5) { v[h][r] = 0ULL; continue; }
                const int mm = j + (r << 10);
                float2 Xm = make_float2(0.0f, 0.0f);
                float2 Cc = make_float2(0.0f, 0.0f);
                if (r < 2) {                       // mm < 2048
                    Xm = __ldg(&orow[mm]);
                    if (mm == 0) Xm.y = 0.0f;      // irfft drops Im(X[0])
                } else {                           // r>=6: mirror branch
                    const int mr = NF - mm;
                    if (mr < MODES) {
                        float2 q = __ldg(&orow[mr]);
                        Cc = make_float2(q.x, -q.y);
                    }
                }
                float2 Ze = make_float2(0.5f * (Xm.x + Cc.x), 0.5f * (Xm.y + Cc.y));
                float2 D  = make_float2(0.5f * (Xm.x - Cc.x), 0.5f * (Xm.y - Cc.y));
                float2 e  = twid((float)mm * BSTEP);
                float2 Zo = cmulf(make_float2(e.x, -e.y), D);
                // Z = Ze + i*Zo ; store conj(Z) so forward FFT computes inverse
                v[h][r] = f2u(make_float2(Ze.x - Zo.y, -(Ze.y + Zo.x)));
            }
            pfft8(v[h]);
        }
#pragma unroll
        for (int h = 0; h < 2; h++) {
            const int base = (tid + (h << 9)) << 3;
#pragma unroll
            for (int r = 0; r < 8; r++) *(ull*)&S[IDX(base + r)] = v[h][r];
        }
        __syncthreads();
    }
    fft_stages12(S);
    // final radix-16: write results straight to gmem (index j + 512r)
    {
        float2 v[16];
        radix16_body(S, tid, v);
        const float sc = 1.0f / 8192.0f;
        float2* outr = (float2*)out + (size_t)row * NF;
#pragma unroll
        for (int r = 0; r < 16; r++) {
            float2 z = v[r];
            outr[tid + (r << 9)] = make_float2(z.x * sc, -z.y * sc); // conj + 1/N
        }
    }
}

// ---------------- launch ----------------------------------------------------
extern "C" void kernel_launch(void* const* d_in, const int* in_sizes, int n_in,
                              void* d_out, int out_size) {
    const float* x    = (const float*)d_in[0];
    const float* temb = (const float*)d_in[1];
    const float* wr   = (const float*)d_in[2];
    const float* wi   = (const float*)d_in[3];
    const float* dw   = (const float*)d_in[4];
    const float* db   = (const float*)d_in[5];
    float* out = (float*)d_out;

    cudaFuncSetAttribute(k_fwd,    cudaFuncAttributeMaxDynamicSharedMemorySize, SBUF * 8);
    cudaFuncSetAttribute(k_inv,    cudaFuncAttributeMaxDynamicSharedMemorySize, SBUF * 8);
    cudaFuncSetAttribute(k_einsum, cudaFuncAttributeMaxDynamicSharedMemorySize, 65536);

    k_bias  <<<BB, 256>>>(temb, dw, db);
    k_fwd   <<<BB * CIN, 512, SBUF * 8>>>(x);
    k_einsum<<<MODES / 8, 256, 65536>>>(wr, wi);
    k_inv   <<<BB * COUT, 512, SBUF * 8>>>(out);
}

// round 12
// speedup vs baseline: 1.0138x; 1.0138x over previous
#include <cuda_runtime.h>
#include <math.h>

#define BB    16
#define CIN   64
#define COUT  64
#define NN    16384
#define NF    8192      // complex FFT size (N/2)
#define MODES 2048
#define TEMB  512

// Skewed shared index: every 8 complexes insert 1 pad -> tames smem bank
// conflicts of the strided Stockham stores.
#define IDX(a) ((a) + ((a) >> 3))
#define SBUF   9216      // IDX(8191)=9214 < 9216  -> 73728 bytes (single buffer)

// ---------------- scratch (static device memory; no allocation) -------------
__device__ float2 g_Xm[BB * CIN * MODES];   // forward modes (+temb bias)
__device__ float2 g_Om[BB * COUT * MODES];  // contracted modes
__device__ float  g_t [BB * CIN];           // temb bias per (b, c_in)

#define ASTEP (-7.66990393942820615e-4f)    // -2*pi/8192
#define BSTEP (-3.83495196971410307e-4f)    // -2*pi/16384

// ---------------- complex helpers -------------------------------------------
__device__ __forceinline__ float2 cmulf(float2 a, float2 b) {
    return make_float2(fmaf(a.x, b.x, -a.y * b.y), fmaf(a.x, b.y, a.y * b.x));
}
__device__ __forceinline__ float2 caddf(float2 a, float2 b) {
    return make_float2(a.x + b.x, a.y + b.y);
}
__device__ __forceinline__ float2 csubf(float2 a, float2 b) {
    return make_float2(a.x - b.x, a.y - b.y);
}
__device__ __forceinline__ float2 twid(float ang) {
    float s, c;
    __sincosf(ang, &s, &c);
    return make_float2(c, s);
}

// packed fp32x2 fma (FFMA2) — used in the einsum only
__device__ __forceinline__ unsigned long long fma2(unsigned long long a,
                                                   unsigned long long b,
                                                   unsigned long long c) {
    unsigned long long d;
    asm("fma.rn.f32x2 %0, %1, %2, %3;" : "=l"(d) : "l"(a), "l"(b), "l"(c));
    return d;
}

// DFT4 (forward, e^{-2pi i rk/4}), natural-order out
__device__ __forceinline__ void dft4(float2 a, float2 b, float2 c, float2 d, float2 y[4]) {
    float2 t0 = caddf(a, c), t1 = csubf(a, c);
    float2 t2 = caddf(b, d), t3 = csubf(b, d);
    y[0] = caddf(t0, t2);
    y[2] = csubf(t0, t2);
    y[1] = make_float2(t1.x + t3.y, t1.y - t3.x);   // t1 - i*t3
    y[3] = make_float2(t1.x - t3.y, t1.y + t3.x);   // t1 + i*t3
}

// DFT8 (forward), natural-order in/out
__device__ __forceinline__ void fft8(float2 v[8]) {
    const float c = 0.70710678118654752f;
    float2 e[4], o[4];
    dft4(v[0], v[2], v[4], v[6], e);
    dft4(v[1], v[3], v[5], v[7], o);
    float2 o0 = o[0];
    float2 o1 = make_float2(c * (o[1].x + o[1].y), c * (o[1].y - o[1].x)); // *(c,-c)
    float2 o2 = make_float2(o[2].y, -o[2].x);                             // *(-i)
    float2 o3 = make_float2(c * (o[3].y - o[3].x), -c * (o[3].x + o[3].y)); // *(-c,-c)
    v[0] = caddf(e[0], o0);  v[4] = csubf(e[0], o0);
    v[1] = caddf(e[1], o1);  v[5] = csubf(e[1], o1);
    v[2] = caddf(e[2], o2);  v[6] = csubf(e[2], o2);
    v[3] = caddf(e[3], o3);  v[7] = csubf(e[3], o3);
}

// DFT16 (forward), natural-order in/out; N1=4 x N2=4 decomposition.
__device__ __forceinline__ void fft16(float2 v[16]) {
    const float c1 = 0.92387953251128675f;   // cos(pi/8)
    const float s1 = 0.38268343236508977f;   // sin(pi/8)
    const float c2 = 0.70710678118654752f;
    float2 y0[4], y1[4], y2[4], y3[4];
    dft4(v[0], v[4], v[8],  v[12], y0);
    dft4(v[1], v[5], v[9],  v[13], y1);
    dft4(v[2], v[6], v[10], v[14], y2);
    dft4(v[3], v[7], v[11], v[15], y3);
    y1[1] = cmulf(y1[1], make_float2( c1, -s1));
    y1[2] = cmulf(y1[2], make_float2( c2, -c2));
    y1[3] = cmulf(y1[3], make_float2( s1, -c1));
    y2[1] = cmulf(y2[1], make_float2( c2, -c2));
    y2[2] = make_float2(y2[2].y, -y2[2].x);                 // * (-i)
    y2[3] = cmulf(y2[3], make_float2(-c2, -c2));
    y3[1] = cmulf(y3[1], make_float2( s1, -c1));
    y3[2] = cmulf(y3[2], make_float2(-c2, -c2));
    y3[3] = cmulf(y3[3], make_float2(-c1,  s1));            // W16^9
    float2 z[4];
    dft4(y0[0], y1[0], y2[0], y3[0], z); v[0]=z[0]; v[4]=z[1]; v[8] =z[2]; v[12]=z[3];
    dft4(y0[1], y1[1], y2[1], y3[1], z); v[1]=z[0]; v[5]=z[1]; v[9] =z[2]; v[13]=z[3];
    dft4(y0[2], y1[2], y2[2], y3[2], z); v[2]=z[0]; v[6]=z[1]; v[10]=z[2]; v[14]=z[3];
    dft4(y0[3], y1[3], y2[3], y3[3], z); v[3]=z[0]; v[7]=z[1]; v[11]=z[2]; v[15]=z[3];
}

// ---- middle radix-8 stages (s = 1, 2) of the 8192-pt Stockham FFT ----------
// Scalar butterflies; twiddles hoisted out of the h loop:
// (tid+512) & (Ns-1) == tid & (Ns-1) for Ns in {8, 64}.
__device__ void fft_stages12(float2* S) {
    const int tid = threadIdx.x;
#pragma unroll
    for (int s = 1; s < 3; s++) {
        const int Ns    = 1 << (3 * s);
        const int shift = 10 - 3 * s;
        const int t = tid & (Ns - 1);
        const float2 w1 = twid((float)(t << shift) * ASTEP);
        const float2 w2 = cmulf(w1, w1);
        const float2 w3 = cmulf(w2, w1);
        const float2 w4 = cmulf(w2, w2);
        const float2 w5 = cmulf(w4, w1);
        const float2 w6 = cmulf(w4, w2);
        const float2 w7 = cmulf(w4, w3);
        float2 v[2][8];
        int base[2];
#pragma unroll
        for (int h = 0; h < 2; h++) {
            const int j = tid + (h << 9);
#pragma unroll
            for (int r = 0; r < 8; r++) v[h][r] = S[IDX(j + (r << 10))];
            v[h][1] = cmulf(v[h][1], w1);
            v[h][2] = cmulf(v[h][2], w2);
            v[h][3] = cmulf(v[h][3], w3);
            v[h][4] = cmulf(v[h][4], w4);
            v[h][5] = cmulf(v[h][5], w5);
            v[h][6] = cmulf(v[h][6], w6);
            v[h][7] = cmulf(v[h][7], w7);
            fft8(v[h]);
            base[h] = ((j >> (3 * s)) << (3 * s + 3)) + t;  // (j/Ns)*8Ns + t
        }
        __syncthreads();
#pragma unroll
        for (int h = 0; h < 2; h++)
#pragma unroll
            for (int r = 0; r < 8; r++)
                S[IDX(base[h] + (r << (3 * s)))] = v[h][r];
        __syncthreads();
    }
}

// ---- final radix-16 butterfly: load from S, twiddle, fft16 -> v[16] --------
__device__ __forceinline__ void radix16_body(const float2* S, int j, float2 v[16]) {
#pragma unroll
    for (int r = 0; r < 16; r++) v[r] = S[IDX(j + (r << 9))];
    const float2 w1 = twid((float)j * ASTEP);
    const float2 w2 = cmulf(w1, w1);
    const float2 w3 = cmulf(w2, w1);
    const float2 w4 = cmulf(w2, w2);
    const float2 w5 = cmulf(w4, w1);
    const float2 w6 = cmulf(w4, w2);
    const float2 w7 = cmulf(w4, w3);
    const float2 w8 = cmulf(w4, w4);
    v[1]  = cmulf(v[1],  w1);
    v[2]  = cmulf(v[2],  w2);
    v[3]  = cmulf(v[3],  w3);
    v[4]  = cmulf(v[4],  w4);
    v[5]  = cmulf(v[5],  w5);
    v[6]  = cmulf(v[6],  w6);
    v[7]  = cmulf(v[7],  w7);
    v[8]  = cmulf(v[8],  w8);
    v[9]  = cmulf(v[9],  cmulf(w8, w1));
    v[10] = cmulf(v[10], cmulf(w8, w2));
    v[11] = cmulf(v[11], cmulf(w8, w3));
    v[12] = cmulf(v[12], cmulf(w8, w4));
    v[13] = cmulf(v[13], cmulf(w8, w5));
    v[14] = cmulf(v[14], cmulf(w8, w6));
    v[15] = cmulf(v[15], cmulf(w8, w7));
    fft16(v);
}

// ---------------- kernel: temb bias t[b,c] ----------------------------------
__global__ void k_bias(const float* __restrict__ temb,
                       const float* __restrict__ dw,
                       const float* __restrict__ db) {
    __shared__ float s_act[TEMB];
    __shared__ float s_part[256];
    const int b = blockIdx.x;
    const int tid = threadIdx.x;
    for (int k = tid; k < TEMB; k += 256) {
        float v = temb[b * TEMB + k];
        s_act[k] = v / (1.0f + expf(-v));          // SiLU
    }
    __syncthreads();
    const int c = tid & 63;
    const int p = tid >> 6;                        // 4 partial chunks of 128
    float sum = 0.0f;
    const float* w = dw + (size_t)c * TEMB;
    for (int k = p * 128; k < (p + 1) * 128; k++) sum = fmaf(s_act[k], w[k], sum);
    s_part[p * 64 + c] = sum;
    __syncthreads();
    if (tid < 64) {
        g_t[b * 64 + tid] = s_part[tid] + s_part[64 + tid] + s_part[128 + tid]
                          + s_part[192 + tid] + db[tid];
    }
}

// ---------------- kernel: forward rFFT + mode extraction + bias -------------
// Stage 0 reads directly from gmem. Tail: modes m=tid+512r (r<4) come straight
// from radix-16 registers; only mirror halves (r>=12) round-trip shared.
// Tail twiddles: ONE sincos, then constant rotations e^{-i pi r/16}.
__global__ void __launch_bounds__(512, 2)
k_fwd(const float* __restrict__ x) {
    extern __shared__ float2 sm[];
    float2* S = sm;
    const int row = blockIdx.x;                    // b*64 + c_in
    const float2* xr = (const float2*)x + (size_t)row * NF;
    const int tid = threadIdx.x;
    // stage 0: Ns=1, twiddle-free, inputs straight from gmem
    {
        float2 v[2][8];
#pragma unroll
        for (int h = 0; h < 2; h++) {
            const int j = tid + (h << 9);
#pragma unroll
            for (int r = 0; r < 8; r++) v[h][r] = __ldg(&xr[j + (r << 10)]);
            fft8(v[h]);
        }
#pragma unroll
        for (int h = 0; h < 2; h++) {
            const int base = (tid + (h << 9)) << 3;
#pragma unroll
            for (int r = 0; r < 8; r++) S[IDX(base + r)] = v[h][r];
        }
        __syncthreads();
    }
    fft_stages12(S);
    float2 v[16];
    radix16_body(S, tid, v);
    __syncthreads();               // stage-2 reads done before overwrite
    // store only the mirror groups r in [12,16): entries 6144..8191
#pragma unroll
    for (int r = 12; r < 16; r++) S[IDX(tid + (r << 9))] = v[r];
    __syncthreads();
    const float tb = g_t[row];
    float2* xrow = g_Xm + (size_t)row * MODES;
    // e^{-2pi i m/16384} = e0 * e^{-i pi r/16},  e0 = e^{-2pi i tid/16384}
    const float2 e0 = twid((float)tid * BSTEP);
    const float2 ER[4] = {
        make_float2(1.0f, 0.0f),
        make_float2(0.98078528040323044f, -0.19509032201612827f),
        make_float2(0.92387953251128675f, -0.38268343236508977f),
        make_float2(0.83146961230254524f, -0.55557023301960222f)
    };
#pragma unroll
    for (int r = 0; r < 4; r++) {
        const int m = tid + (r << 9);
        float2 Zm = v[r];
        float2 Zn;
        if (tid == 0) {
            Zn = (r == 0) ? v[0] : v[16 - r];       // Z[8192-512r] is own reg
        } else {
            // 8192-m = (512-tid) + 512*(15-r) -> stored by thread 512-tid
            Zn = S[IDX((512 - tid) + ((15 - r) << 9))];
        }
        float2 A  = make_float2(Zm.x + Zn.x, Zm.y - Zn.y);   // Z + conj(Zn)
        float2 Bc = make_float2(Zm.x - Zn.x, Zm.y + Zn.y);   // Z - conj(Zn)
        float2 C  = cmulf(cmulf(e0, ER[r]), Bc);
        // X = 0.5*A - 0.5*i*C ; add temb bias to real part
        xrow[m] = make_float2(0.5f * (A.x + C.y) + tb, 0.5f * (A.y - C.x));
    }
}

// ---------------- kernel: mode contraction (bim,iom->bom) -------------------
// grid: 256 blocks (8 modes each); block: 256 threads =
//   [bit7]=batch-half x [bits2:7]=32 o-pairs x [bits0:2]=4 mode-pairs.
// Round-8 layout + prefetch.global.L2 at distance 4 (verified winner).
__global__ void __launch_bounds__(256, 2)
k_einsum(const float* __restrict__ wr, const float* __restrict__ wi) {
    extern __shared__ float4 Xc[];                 // [ (b*64+i)*4 + mg ] 64KB
    const int m0  = blockIdx.x * 8;
    const int tid = threadIdx.x;
    for (int idx = tid; idx < BB * CIN * 4; idx += 256) {
        const int p  = idx & 3;
        const int bi = idx >> 2;
        float4 q = *((const float4*)(g_Xm + (size_t)bi * MODES + m0) + p);
        Xc[idx] = make_float4(q.x, q.z, q.y, q.w); // (re0, re1, im0, im1)
    }
    __syncthreads();
    const int mg = tid & 3;
    const int op = (tid >> 2) & 31;
    const int bh = tid >> 7;
    const int o0 = 2 * op;
    const int m  = m0 + 2 * mg;
    const int b0 = bh * 8;

    unsigned long long ar[2][8], ai[2][8];
#pragma unroll
    for (int k = 0; k < 2; k++)
#pragma unroll
        for (int b = 0; b < 8; b++) { ar[k][b] = 0ULL; ai[k][b] = 0ULL; }

    const size_t istep = (size_t)COUT * MODES;
    size_t off = (size_t)o0 * MODES + m;
    unsigned long long cwr0 = *(const unsigned long long*)(wr + off);
    unsigned long long cwr1 = *(const unsigned long long*)(wr + off + MODES);
    unsigned long long cwi0 = *(const unsigned long long*)(wi + off);
    unsigned long long cwi1 = *(const unsigned long long*)(wi + off + MODES);

    for (int i = 0; i < CIN; i++) {
        unsigned long long nwr0, nwr1, nwi0, nwi1;
        if (i + 1 < CIN) {                          // register prefetch, d=1
            const size_t noff = off + istep;
            nwr0 = *(const unsigned long long*)(wr + noff);
            nwr1 = *(const unsigned long long*)(wr + noff + MODES);
            nwi0 = *(const unsigned long long*)(wi + noff);
            nwi1 = *(const unsigned long long*)(wi + noff + MODES);
        }
        if (i + 4 < CIN) {                          // L2 prefetch, distance 4
            const size_t poff = off + 4 * istep;
            asm volatile("prefetch.global.L2 [%0];" :: "l"(wr + poff));
            asm volatile("prefetch.global.L2 [%0];" :: "l"(wr + poff + MODES));
            asm volatile("prefetch.global.L2 [%0];" :: "l"(wi + poff));
            asm volatile("prefetch.global.L2 [%0];" :: "l"(wi + poff + MODES));
        }
#pragma unroll
        for (int b = 0; b < 8; b++) {
            const int idx2 = ((b0 + b) * CIN + i) * 4 + mg;
            const ulonglong2 xu = *(const ulonglong2*)(Xc + idx2); // 1 LDS.128
            const unsigned long long xr2  = xu.x;                  // (re0,re1)
            const unsigned long long xi2  = xu.y;                  // (im0,im1)
            const unsigned long long xin2 = xi2 ^ 0x8000000080000000ULL;
            ar[0][b] = fma2(xr2,  cwr0, ar[0][b]);
            ar[0][b] = fma2(xin2, cwi0, ar[0][b]);
            ai[0][b] = fma2(xr2,  cwi0, ai[0][b]);
            ai[0][b] = fma2(xi2,  cwr0, ai[0][b]);
            ar[1][b] = fma2(xr2,  cwr1, ar[1][b]);
            ar[1][b] = fma2(xin2, cwi1, ar[1][b]);
            ai[1][b] = fma2(xr2,  cwi1, ai[1][b]);
            ai[1][b] = fma2(xi2,  cwr1, ai[1][b]);
        }
        cwr0 = nwr0; cwr1 = nwr1; cwi0 = nwi0; cwi1 = nwi1;
        off += istep;
    }
#pragma unroll
    for (int k = 0; k < 2; k++)
#pragma unroll
        for (int b = 0; b < 8; b++) {
            float r0, r1, i0, i1;
            asm("mov.b64 {%0, %1}, %2;" : "=f"(r0), "=f"(r1) : "l"(ar[k][b]));
            asm("mov.b64 {%0, %1}, %2;" : "=f"(i0), "=f"(i1) : "l"(ai[k][b]));
            const size_t ob = ((size_t)((b0 + b) * COUT + o0 + k)) * MODES + m;
            *((float4*)(g_Om + ob)) = make_float4(r0, i0, r1, i1);
        }
}

// ---------------- kernel: inverse rFFT --------------------------------------
// Stage 0 builds the Hermitian-packed spectrum in REGISTERS from g_Om
// (only r in {0,1,6,7} nonzero); final radix-16 writes straight to gmem.
// Stage-0 twiddles: ONE sincos per half, then constant rotations e^{-i pi r/8}.
__global__ void __launch_bounds__(512, 2)
k_inv(float* __restrict__ out) {
    extern __shared__ float2 sm[];
    float2* S = sm;
    const int row = blockIdx.x;                    // b*64 + c_out
    const float2* orow = g_Om + (size_t)row * MODES;
    const int tid = threadIdx.x;
    // stage 0 (Ns=1, twiddle-free): inputs computed inline
    {
        float2 v[2][8];
#pragma unroll
        for (int h = 0; h < 2; h++) {
            const int j = tid + (h << 9);
            const float2 e0 = twid((float)j * BSTEP);  // e^{-2pi i j/16384}
#pragma unroll
            for (int r = 0; r < 8; r++) {
                if (r >= 2 && r <= 5) { v[h][r] = make_float2(0.0f, 0.0f); continue; }
                const int mm = j + (r << 10);
                float2 Xm = make_float2(0.0f, 0.0f);
                float2 Cc = make_float2(0.0f, 0.0f);
                if (r < 2) {                       // mm < 2048
                    Xm = __ldg(&orow[mm]);
                    if (mm == 0) Xm.y = 0.0f;      // irfft drops Im(X[0])
                } else {                           // r>=6: mirror branch
                    const int mr = NF - mm;
                    if (mr < MODES) {
                        float2 q = __ldg(&orow[mr]);
                        Cc = make_float2(q.x, -q.y);
                    }
                }
                float2 Ze = make_float2(0.5f * (Xm.x + Cc.x), 0.5f * (Xm.y + Cc.y));
                float2 D  = make_float2(0.5f * (Xm.x - Cc.x), 0.5f * (Xm.y - Cc.y));
                // e = e0 * e^{-i pi r/8} (constants for r in {0,1,6,7})
                float2 er;
                if (r == 0)      er = e0;
                else if (r == 1) er = cmulf(e0, make_float2( 0.92387953251128675f, -0.38268343236508977f));
                else if (r == 6) er = cmulf(e0, make_float2(-0.70710678118654752f, -0.70710678118654752f));
                else             er = cmulf(e0, make_float2(-0.92387953251128675f, -0.38268343236508977f));
                float2 Zo = cmulf(make_float2(er.x, -er.y), D);
                // Z = Ze + i*Zo ; store conj(Z) so forward FFT computes inverse
                v[h][r] = make_float2(Ze.x - Zo.y, -(Ze.y + Zo.x));
            }
            fft8(v[h]);
        }
#pragma unroll
        for (int h = 0; h < 2; h++) {
            const int base = (tid + (h << 9)) << 3;
#pragma unroll
            for (int r = 0; r < 8; r++) S[IDX(base + r)] = v[h][r];
        }
        __syncthreads();
    }
    fft_stages12(S);
    // final radix-16: write results straight to gmem (index j + 512r)
    {
        float2 v[16];
        radix16_body(S, tid, v);
        const float sc = 1.0f / 8192.0f;
        float2* outr = (float2*)out + (size_t)row * NF;
#pragma unroll
        for (int r = 0; r < 16; r++) {
            float2 z = v[r];
            outr[tid + (r << 9)] = make_float2(z.x * sc, -z.y * sc); // conj + 1/N
        }
    }
}

// ---------------- launch ----------------------------------------------------
extern "C" void kernel_launch(void* const* d_in, const int* in_sizes, int n_in,
                              void* d_out, int out_size) {
    const float* x    = (const float*)d_in[0];
    const float* temb = (const float*)d_in[1];
    const float* wr   = (const float*)d_in[2];
    const float* wi   = (const float*)d_in[3];
    const float* dw   = (const float*)d_in[4];
    const float* db   = (const float*)d_in[5];
    float* out = (float*)d_out;

    cudaFuncSetAttribute(k_fwd,    cudaFuncAttributeMaxDynamicSharedMemorySize, SBUF * 8);
    cudaFuncSetAttribute(k_inv,    cudaFuncAttributeMaxDynamicSharedMemorySize, SBUF * 8);
    cudaFuncSetAttribute(k_einsum, cudaFuncAttributeMaxDynamicSharedMemorySize, 65536);

    k_bias  <<<BB, 256>>>(temb, dw, db);
    k_fwd   <<<BB * CIN, 512, SBUF * 8>>>(x);
    k_einsum<<<MODES / 8, 256, 65536>>>(wr, wi);
    k_inv   <<<BB * COUT, 512, SBUF * 8>>>(out);
}

// round 13
// speedup vs baseline: 1.1479x; 1.1322x over previous
#include <cuda_runtime.h>
#include <math.h>

#define BB    16
#define CIN   64
#define COUT  64
#define NN    16384
#define NF    8192      // complex FFT size (N/2)
#define MODES 2048
#define TEMB  512

// Skewed shared index: every 8 complexes insert 1 pad -> tames smem bank
// conflicts of the strided Stockham stores.
#define IDX(a) ((a) + ((a) >> 3))
#define SBUF   9216      // IDX(8191)=9214 < 9216  -> 73728 bytes (single buffer)

// ---------------- scratch (static device memory; no allocation) -------------
__device__ float2 g_Xm[BB * CIN * MODES];   // forward modes (+temb bias)
__device__ float2 g_Om[BB * COUT * MODES];  // contracted modes

#define ASTEP (-7.66990393942820615e-4f)    // -2*pi/8192
#define BSTEP (-3.83495196971410307e-4f)    // -2*pi/16384

// ---------------- complex helpers -------------------------------------------
__device__ __forceinline__ float2 cmulf(float2 a, float2 b) {
    return make_float2(fmaf(a.x, b.x, -a.y * b.y), fmaf(a.x, b.y, a.y * b.x));
}
__device__ __forceinline__ float2 caddf(float2 a, float2 b) {
    return make_float2(a.x + b.x, a.y + b.y);
}
__device__ __forceinline__ float2 csubf(float2 a, float2 b) {
    return make_float2(a.x - b.x, a.y - b.y);
}
__device__ __forceinline__ float2 twid(float ang) {
    float s, c;
    __sincosf(ang, &s, &c);
    return make_float2(c, s);
}

// packed fp32x2 fma (FFMA2) — used in the einsum only
__device__ __forceinline__ unsigned long long fma2(unsigned long long a,
                                                   unsigned long long b,
                                                   unsigned long long c) {
    unsigned long long d;
    asm("fma.rn.f32x2 %0, %1, %2, %3;" : "=l"(d) : "l"(a), "l"(b), "l"(c));
    return d;
}

// DFT4 (forward, e^{-2pi i rk/4}), natural-order out
__device__ __forceinline__ void dft4(float2 a, float2 b, float2 c, float2 d, float2 y[4]) {
    float2 t0 = caddf(a, c), t1 = csubf(a, c);
    float2 t2 = caddf(b, d), t3 = csubf(b, d);
    y[0] = caddf(t0, t2);
    y[2] = csubf(t0, t2);
    y[1] = make_float2(t1.x + t3.y, t1.y - t3.x);   // t1 - i*t3
    y[3] = make_float2(t1.x - t3.y, t1.y + t3.x);   // t1 + i*t3
}

// DFT8 (forward), natural-order in/out
__device__ __forceinline__ void fft8(float2 v[8]) {
    const float c = 0.70710678118654752f;
    float2 e[4], o[4];
    dft4(v[0], v[2], v[4], v[6], e);
    dft4(v[1], v[3], v[5], v[7], o);
    float2 o0 = o[0];
    float2 o1 = make_float2(c * (o[1].x + o[1].y), c * (o[1].y - o[1].x)); // *(c,-c)
    float2 o2 = make_float2(o[2].y, -o[2].x);                             // *(-i)
    float2 o3 = make_float2(c * (o[3].y - o[3].x), -c * (o[3].x + o[3].y)); // *(-c,-c)
    v[0] = caddf(e[0], o0);  v[4] = csubf(e[0], o0);
    v[1] = caddf(e[1], o1);  v[5] = csubf(e[1], o1);
    v[2] = caddf(e[2], o2);  v[6] = csubf(e[2], o2);
    v[3] = caddf(e[3], o3);  v[7] = csubf(e[3], o3);
}

// ---- shared stage-1 of DFT16 (4 dft4s + constant twiddles) -----------------
__device__ __forceinline__ void fft16_stage1(const float2 v[16],
                                             float2 y0[4], float2 y1[4],
                                             float2 y2[4], float2 y3[4]) {
    const float c1 = 0.92387953251128675f;   // cos(pi/8)
    const float s1 = 0.38268343236508977f;   // sin(pi/8)
    const float c2 = 0.70710678118654752f;
    dft4(v[0], v[4], v[8],  v[12], y0);
    dft4(v[1], v[5], v[9],  v[13], y1);
    dft4(v[2], v[6], v[10], v[14], y2);
    dft4(v[3], v[7], v[11], v[15], y3);
    y1[1] = cmulf(y1[1], make_float2( c1, -s1));
    y1[2] = cmulf(y1[2], make_float2( c2, -c2));
    y1[3] = cmulf(y1[3], make_float2( s1, -c1));
    y2[1] = cmulf(y2[1], make_float2( c2, -c2));
    y2[2] = make_float2(y2[2].y, -y2[2].x);                 // * (-i)
    y2[3] = cmulf(y2[3], make_float2(-c2, -c2));
    y3[1] = cmulf(y3[1], make_float2( s1, -c1));
    y3[2] = cmulf(y3[2], make_float2(-c2, -c2));
    y3[3] = cmulf(y3[3], make_float2(-c1,  s1));            // W16^9
}

// DFT16 (forward), natural-order in/out; full 16 outputs (inverse path).
__device__ __forceinline__ void fft16(float2 v[16]) {
    float2 y0[4], y1[4], y2[4], y3[4];
    fft16_stage1(v, y0, y1, y2, y3);
    float2 z[4];
    dft4(y0[0], y1[0], y2[0], y3[0], z); v[0]=z[0]; v[4]=z[1]; v[8] =z[2]; v[12]=z[3];
    dft4(y0[1], y1[1], y2[1], y3[1], z); v[1]=z[0]; v[5]=z[1]; v[9] =z[2]; v[13]=z[3];
    dft4(y0[2], y1[2], y2[2], y3[2], z); v[2]=z[0]; v[6]=z[1]; v[10]=z[2]; v[14]=z[3];
    dft4(y0[3], y1[3], y2[3], y3[3], z); v[3]=z[0]; v[7]=z[1]; v[11]=z[2]; v[15]=z[3];
}

// DFT16 pruned for the forward path: only outputs r in {0..3, 12..15}.
// Final dft4 bank emits z0 = t0+t2 and z3 = t1+i*t3 only (6 adds vs 8).
__device__ __forceinline__ void fft16_fwd(float2 v[16]) {
    float2 y0[4], y1[4], y2[4], y3[4];
    fft16_stage1(v, y0, y1, y2, y3);
#pragma unroll
    for (int k = 0; k < 4; k++) {
        float2 t0 = caddf(y0[k], y2[k]), t1 = csubf(y0[k], y2[k]);
        float2 t2 = caddf(y1[k], y3[k]), t3 = csubf(y1[k], y3[k]);
        v[k]      = caddf(t0, t2);
        v[k + 12] = make_float2(t1.x - t3.y, t1.y + t3.x);   // t1 + i*t3
    }
}

// ---- middle radix-8 stages (s = 1, 2) of the 8192-pt Stockham FFT ----------
// Scalar butterflies; twiddles hoisted out of the h loop:
// (tid+512) & (Ns-1) == tid & (Ns-1) for Ns in {8, 64}.
__device__ void fft_stages12(float2* S) {
    const int tid = threadIdx.x;
#pragma unroll
    for (int s = 1; s < 3; s++) {
        const int Ns    = 1 << (3 * s);
        const int shift = 10 - 3 * s;
        const int t = tid & (Ns - 1);
        const float2 w1 = twid((float)(t << shift) * ASTEP);
        const float2 w2 = cmulf(w1, w1);
        const float2 w3 = cmulf(w2, w1);
        const float2 w4 = cmulf(w2, w2);
        const float2 w5 = cmulf(w4, w1);
        const float2 w6 = cmulf(w4, w2);
        const float2 w7 = cmulf(w4, w3);
        float2 v[2][8];
        int base[2];
#pragma unroll
        for (int h = 0; h < 2; h++) {
            const int j = tid + (h << 9);
#pragma unroll
            for (int r = 0; r < 8; r++) v[h][r] = S[IDX(j + (r << 10))];
            v[h][1] = cmulf(v[h][1], w1);
            v[h][2] = cmulf(v[h][2], w2);
            v[h][3] = cmulf(v[h][3], w3);
            v[h][4] = cmulf(v[h][4], w4);
            v[h][5] = cmulf(v[h][5], w5);
            v[h][6] = cmulf(v[h][6], w6);
            v[h][7] = cmulf(v[h][7], w7);
            fft8(v[h]);
            base[h] = ((j >> (3 * s)) << (3 * s + 3)) + t;  // (j/Ns)*8Ns + t
        }
        __syncthreads();
#pragma unroll
        for (int h = 0; h < 2; h++)
#pragma unroll
            for (int r = 0; r < 8; r++)
                S[IDX(base[h] + (r << (3 * s)))] = v[h][r];
        __syncthreads();
    }
}

// ---- final radix-16 load + twiddle (shared by fwd/inv) ---------------------
__device__ __forceinline__ void radix16_load(const float2* S, int j, float2 v[16]) {
#pragma unroll
    for (int r = 0; r < 16; r++) v[r] = S[IDX(j + (r << 9))];
    const float2 w1 = twid((float)j * ASTEP);
    const float2 w2 = cmulf(w1, w1);
    const float2 w3 = cmulf(w2, w1);
    const float2 w4 = cmulf(w2, w2);
    const float2 w5 = cmulf(w4, w1);
    const float2 w6 = cmulf(w4, w2);
    const float2 w7 = cmulf(w4, w3);
    const float2 w8 = cmulf(w4, w4);
    v[1]  = cmulf(v[1],  w1);
    v[2]  = cmulf(v[2],  w2);
    v[3]  = cmulf(v[3],  w3);
    v[4]  = cmulf(v[4],  w4);
    v[5]  = cmulf(v[5],  w5);
    v[6]  = cmulf(v[6],  w6);
    v[7]  = cmulf(v[7],  w7);
    v[8]  = cmulf(v[8],  w8);
    v[9]  = cmulf(v[9],  cmulf(w8, w1));
    v[10] = cmulf(v[10], cmulf(w8, w2));
    v[11] = cmulf(v[11], cmulf(w8, w3));
    v[12] = cmulf(v[12], cmulf(w8, w4));
    v[13] = cmulf(v[13], cmulf(w8, w5));
    v[14] = cmulf(v[14], cmulf(w8, w6));
    v[15] = cmulf(v[15], cmulf(w8, w7));
}

// ---------------- kernel: forward rFFT + temb bias (fused) + modes ----------
// Per-CTA bias dot product overlapped with stage-0 gmem loads. Stage 0 reads
// directly from gmem (.cs: read-once). Tail: modes m=tid+512r (r<4) come from
// radix-16 registers (pruned fft16); mirror halves (r>=12) round-trip shared.
__global__ void __launch_bounds__(512, 2)
k_fwd(const float* __restrict__ x, const float* __restrict__ temb,
      const float* __restrict__ dw, const float* __restrict__ db) {
    extern __shared__ float2 sm[];
    float2* S = sm;
    __shared__ float s_part[16];
    __shared__ float s_bias;
    const int row = blockIdx.x;                    // b*64 + c_in
    const int bb  = row >> 6;
    const int cc  = row & 63;
    const float2* xr = (const float2*)x + (size_t)row * NF;
    const int tid = threadIdx.x;

    // ---- bias partial: one product per thread (TEMB == 512 == blockDim) ----
    {
        float tv = __ldg(&temb[bb * TEMB + tid]);
        float act = tv / (1.0f + expf(-tv));       // SiLU
        float prod = act * __ldg(&dw[(size_t)cc * TEMB + tid]);
#pragma unroll
        for (int o = 16; o; o >>= 1) prod += __shfl_xor_sync(0xffffffffu, prod, o);
        if ((tid & 31) == 0) s_part[tid >> 5] = prod;
    }

    // stage 0: Ns=1, twiddle-free, inputs straight from gmem (streaming)
    {
        float2 v[2][8];
#pragma unroll
        for (int h = 0; h < 2; h++) {
            const int j = tid + (h << 9);
#pragma unroll
            for (int r = 0; r < 8; r++) v[h][r] = __ldcs(&xr[j + (r << 10)]);
            fft8(v[h]);
        }
#pragma unroll
        for (int h = 0; h < 2; h++) {
            const int base = (tid + (h << 9)) << 3;
#pragma unroll
            for (int r = 0; r < 8; r++) S[IDX(base + r)] = v[h][r];
        }
        __syncthreads();                           // also publishes s_part
    }
    if (tid == 0) {                                // finish bias reduction
        float sum = __ldg(&db[cc]);
#pragma unroll
        for (int w = 0; w < 16; w++) sum += s_part[w];
        s_bias = sum;                              // read after later barriers
    }
    fft_stages12(S);
    float2 v[16];
    radix16_load(S, tid, v);
    fft16_fwd(v);                                  // only r in {0..3, 12..15}
    __syncthreads();               // stage-2 reads done before overwrite
    // store only the mirror groups r in [12,16): entries 6144..8191
#pragma unroll
    for (int r = 12; r < 16; r++) S[IDX(tid + (r << 9))] = v[r];
    __syncthreads();
    const float tb = s_bias;
    float2* xrow = g_Xm + (size_t)row * MODES;
    // e^{-2pi i m/16384} = e0 * e^{-i pi r/16},  e0 = e^{-2pi i tid/16384}
    const float2 e0 = twid((float)tid * BSTEP);
    const float2 ER[4] = {
        make_float2(1.0f, 0.0f),
        make_float2(0.98078528040323044f, -0.19509032201612827f),
        make_float2(0.92387953251128675f, -0.38268343236508977f),
        make_float2(0.83146961230254524f, -0.55557023301960222f)
    };
#pragma unroll
    for (int r = 0; r < 4; r++) {
        const int m = tid + (r << 9);
        float2 Zm = v[r];
        float2 Zn;
        if (tid == 0) {
            Zn = (r == 0) ? v[0] : v[16 - r];       // Z[8192-512r] is own reg
        } else {
            // 8192-m = (512-tid) + 512*(15-r) -> stored by thread 512-tid
            Zn = S[IDX((512 - tid) + ((15 - r) << 9))];
        }
        float2 A  = make_float2(Zm.x + Zn.x, Zm.y - Zn.y);   // Z + conj(Zn)
        float2 Bc = make_float2(Zm.x - Zn.x, Zm.y + Zn.y);   // Z - conj(Zn)
        float2 C  = cmulf(cmulf(e0, ER[r]), Bc);
        // X = 0.5*A - 0.5*i*C ; add temb bias to real part
        xrow[m] = make_float2(0.5f * (A.x + C.y) + tb, 0.5f * (A.y - C.x));
    }
}

// ---------------- kernel: mode contraction (bim,iom->bom) -------------------
// grid: 256 blocks (8 modes each); block: 256 threads =
//   [bit7]=batch-half x [bits2:7]=32 o-pairs x [bits0:2]=4 mode-pairs.
// Round-8 layout + prefetch.global.L2 at distance 4 (verified winner).
__global__ void __launch_bounds__(256, 2)
k_einsum(const float* __restrict__ wr, const float* __restrict__ wi) {
    extern __shared__ float4 Xc[];                 // [ (b*64+i)*4 + mg ] 64KB
    const int m0  = blockIdx.x * 8;
    const int tid = threadIdx.x;
    for (int idx = tid; idx < BB * CIN * 4; idx += 256) {
        const int p  = idx & 3;
        const int bi = idx >> 2;
        float4 q = *((const float4*)(g_Xm + (size_t)bi * MODES + m0) + p);
        Xc[idx] = make_float4(q.x, q.z, q.y, q.w); // (re0, re1, im0, im1)
    }
    __syncthreads();
    const int mg = tid & 3;
    const int op = (tid >> 2) & 31;
    const int bh = tid >> 7;
    const int o0 = 2 * op;
    const int m  = m0 + 2 * mg;
    const int b0 = bh * 8;

    unsigned long long ar[2][8], ai[2][8];
#pragma unroll
    for (int k = 0; k < 2; k++)
#pragma unroll
        for (int b = 0; b < 8; b++) { ar[k][b] = 0ULL; ai[k][b] = 0ULL; }

    const size_t istep = (size_t)COUT * MODES;
    size_t off = (size_t)o0 * MODES + m;
    unsigned long long cwr0 = *(const unsigned long long*)(wr + off);
    unsigned long long cwr1 = *(const unsigned long long*)(wr + off + MODES);
    unsigned long long cwi0 = *(const unsigned long long*)(wi + off);
    unsigned long long cwi1 = *(const unsigned long long*)(wi + off + MODES);

    for (int i = 0; i < CIN; i++) {
        unsigned long long nwr0, nwr1, nwi0, nwi1;
        if (i + 1 < CIN) {                          // register prefetch, d=1
            const size_t noff = off + istep;
            nwr0 = *(const unsigned long long*)(wr + noff);
            nwr1 = *(const unsigned long long*)(wr + noff + MODES);
            nwi0 = *(const unsigned long long*)(wi + noff);
            nwi1 = *(const unsigned long long*)(wi + noff + MODES);
        }
        if (i + 4 < CIN) {                          // L2 prefetch, distance 4
            const size_t poff = off + 4 * istep;
            asm volatile("prefetch.global.L2 [%0];" :: "l"(wr + poff));
            asm volatile("prefetch.global.L2 [%0];" :: "l"(wr + poff + MODES));
            asm volatile("prefetch.global.L2 [%0];" :: "l"(wi + poff));
            asm volatile("prefetch.global.L2 [%0];" :: "l"(wi + poff + MODES));
        }
#pragma unroll
        for (int b = 0; b < 8; b++) {
            const int idx2 = ((b0 + b) * CIN + i) * 4 + mg;
            const ulonglong2 xu = *(const ulonglong2*)(Xc + idx2); // 1 LDS.128
            const unsigned long long xr2  = xu.x;                  // (re0,re1)
            const unsigned long long xi2  = xu.y;                  // (im0,im1)
            const unsigned long long xin2 = xi2 ^ 0x8000000080000000ULL;
            ar[0][b] = fma2(xr2,  cwr0, ar[0][b]);
            ar[0][b] = fma2(xin2, cwi0, ar[0][b]);
            ai[0][b] = fma2(xr2,  cwi0, ai[0][b]);
            ai[0][b] = fma2(xi2,  cwr0, ai[0][b]);
            ar[1][b] = fma2(xr2,  cwr1, ar[1][b]);
            ar[1][b] = fma2(xin2, cwi1, ar[1][b]);
            ai[1][b] = fma2(xr2,  cwi1, ai[1][b]);
            ai[1][b] = fma2(xi2,  cwr1, ai[1][b]);
        }
        cwr0 = nwr0; cwr1 = nwr1; cwi0 = nwi0; cwi1 = nwi1;
        off += istep;
    }
#pragma unroll
    for (int k = 0; k < 2; k++)
#pragma unroll
        for (int b = 0; b < 8; b++) {
            float r0, r1, i0, i1;
            asm("mov.b64 {%0, %1}, %2;" : "=f"(r0), "=f"(r1) : "l"(ar[k][b]));
            asm("mov.b64 {%0, %1}, %2;" : "=f"(i0), "=f"(i1) : "l"(ai[k][b]));
            const size_t ob = ((size_t)((b0 + b) * COUT + o0 + k)) * MODES + m;
            *((float4*)(g_Om + ob)) = make_float4(r0, i0, r1, i1);
        }
}

// ---------------- kernel: inverse rFFT --------------------------------------
// Stage 0 builds the Hermitian-packed spectrum in REGISTERS from g_Om
// (only r in {0,1,6,7} nonzero); final radix-16 writes straight to gmem (.cs).
// Stage-0 twiddles: ONE sincos per half, then constant rotations e^{-i pi r/8}.
__global__ void __launch_bounds__(512, 2)
k_inv(float* __restrict__ out) {
    extern __shared__ float2 sm[];
    float2* S = sm;
    const int row = blockIdx.x;                    // b*64 + c_out
    const float2* orow = g_Om + (size_t)row * MODES;
    const int tid = threadIdx.x;
    // stage 0 (Ns=1, twiddle-free): inputs computed inline
    {
        float2 v[2][8];
#pragma unroll
        for (int h = 0; h < 2; h++) {
            const int j = tid + (h << 9);
            const float2 e0 = twid((float)j * BSTEP);  // e^{-2pi i j/16384}
#pragma unroll
            for (int r = 0; r < 8; r++) {
                if (r >= 2 && r <= 5) { v[h][r] = make_float2(0.0f, 0.0f); continue; }
                const int mm = j + (r << 10);
                float2 Xm = make_float2(0.0f, 0.0f);
                float2 Cc = make_float2(0.0f, 0.0f);
                if (r < 2) {                       // mm < 2048
                    Xm = __ldg(&orow[mm]);
                    if (mm == 0) Xm.y = 0.0f;      // irfft drops Im(X[0])
                } else {                           // r>=6: mirror branch
                    const int mr = NF - mm;
                    if (mr < MODES) {
                        float2 q = __ldg(&orow[mr]);
                        Cc = make_float2(q.x, -q.y);
                    }
                }
                float2 Ze = make_float2(0.5f * (Xm.x + Cc.x), 0.5f * (Xm.y + Cc.y));
                float2 D  = make_float2(0.5f * (Xm.x - Cc.x), 0.5f * (Xm.y - Cc.y));
                // e = e0 * e^{-i pi r/8} (constants for r in {0,1,6,7})
                float2 er;
                if (r == 0)      er = e0;
                else if (r == 1) er = cmulf(e0, make_float2( 0.92387953251128675f, -0.38268343236508977f));
                else if (r == 6) er = cmulf(e0, make_float2(-0.70710678118654752f, -0.70710678118654752f));
                else             er = cmulf(e0, make_float2(-0.92387953251128675f, -0.38268343236508977f));
                float2 Zo = cmulf(make_float2(er.x, -er.y), D);
                // Z = Ze + i*Zo ; store conj(Z) so forward FFT computes inverse
                v[h][r] = make_float2(Ze.x - Zo.y, -(Ze.y + Zo.x));
            }
            fft8(v[h]);
        }
#pragma unroll
        for (int h = 0; h < 2; h++) {
            const int base = (tid + (h << 9)) << 3;
#pragma unroll
            for (int r = 0; r < 8; r++) S[IDX(base + r)] = v[h][r];
        }
        __syncthreads();
    }
    fft_stages12(S);
    // final radix-16: write results straight to gmem (index j + 512r)
    {
        float2 v[16];
        radix16_load(S, tid, v);
        fft16(v);
        const float sc = 1.0f / 8192.0f;
        float2* outr = (float2*)out + (size_t)row * NF;
#pragma unroll
        for (int r = 0; r < 16; r++) {
            float2 z = v[r];
            __stcs(&outr[tid + (r << 9)],
                   make_float2(z.x * sc, -z.y * sc));   // conj + 1/N, streaming
        }
    }
}

// ---------------- launch ----------------------------------------------------
extern "C" void kernel_launch(void* const* d_in, const int* in_sizes, int n_in,
                              void* d_out, int out_size) {
    const float* x    = (const float*)d_in[0];
    const float* temb = (const float*)d_in[1];
    const float* wr   = (const float*)d_in[2];
    const float* wi   = (const float*)d_in[3];
    const float* dw   = (const float*)d_in[4];
    const float* db   = (const float*)d_in[5];
    float* out = (float*)d_out;

    cudaFuncSetAttribute(k_fwd,    cudaFuncAttributeMaxDynamicSharedMemorySize, SBUF * 8);
    cudaFuncSetAttribute(k_inv,    cudaFuncAttributeMaxDynamicSharedMemorySize, SBUF * 8);
    cudaFuncSetAttribute(k_einsum, cudaFuncAttributeMaxDynamicSharedMemorySize, 65536);

    k_fwd   <<<BB * CIN, 512, SBUF * 8>>>(x, temb, dw, db);
    k_einsum<<<MODES / 8, 256, 65536>>>(wr, wi);
    k_inv   <<<BB * COUT, 512, SBUF * 8>>>(out);
}